// round 2
// baseline (speedup 1.0000x reference)
#include <cuda_runtime.h>
#include <stdint.h>

// out[i] = Param_b[b_params[i]]  (bias init, also clears the 0xAA poison)
__global__ void bias_init_kernel(const float* __restrict__ Param_b,
                                 const int* __restrict__ b_params,
                                 float* __restrict__ out, int n) {
    int i = blockIdx.x * blockDim.x + threadIdx.x;
    if (i < n) {
        out[i] = __ldg(&Param_b[b_params[i]]);
    }
}

// Each thread handles 4 edges via int4 loads of the three index streams.
// vals = Param_W[p] * x[c]; RED-add into out[r].
__global__ void edge_scatter_kernel(const float* __restrict__ x,
                                    const float* __restrict__ Param_W,
                                    const int4* __restrict__ w_rows4,
                                    const int4* __restrict__ w_cols4,
                                    const int4* __restrict__ w_params4,
                                    float* __restrict__ out, int e4) {
    int i = blockIdx.x * blockDim.x + threadIdx.x;
    if (i >= e4) return;

    int4 r = __ldg(&w_rows4[i]);
    int4 c = __ldg(&w_cols4[i]);
    int4 p = __ldg(&w_params4[i]);

    // Gather first (maximize MLP before the dependent atomics)
    float xw0 = __ldg(&x[c.x]);
    float xw1 = __ldg(&x[c.y]);
    float xw2 = __ldg(&x[c.z]);
    float xw3 = __ldg(&x[c.w]);
    float pw0 = __ldg(&Param_W[p.x]);
    float pw1 = __ldg(&Param_W[p.y]);
    float pw2 = __ldg(&Param_W[p.z]);
    float pw3 = __ldg(&Param_W[p.w]);

    atomicAdd(&out[r.x], pw0 * xw0);
    atomicAdd(&out[r.y], pw1 * xw1);
    atomicAdd(&out[r.z], pw2 * xw2);
    atomicAdd(&out[r.w], pw3 * xw3);
}

// Tail path (E not divisible by 4 — not expected here, but kept safe)
__global__ void edge_scatter_tail_kernel(const float* __restrict__ x,
                                         const float* __restrict__ Param_W,
                                         const int* __restrict__ w_rows,
                                         const int* __restrict__ w_cols,
                                         const int* __restrict__ w_params,
                                         float* __restrict__ out,
                                         int start, int e) {
    int i = start + blockIdx.x * blockDim.x + threadIdx.x;
    if (i < e) {
        atomicAdd(&out[w_rows[i]], __ldg(&Param_W[w_params[i]]) * __ldg(&x[w_cols[i]]));
    }
}

extern "C" void kernel_launch(void* const* d_in, const int* in_sizes, int n_in,
                              void* d_out, int out_size) {
    // metadata order: x, Param_W, Param_b, w_rows, w_cols, w_params, b_params
    const float* x        = (const float*)d_in[0];
    const float* Param_W  = (const float*)d_in[1];
    const float* Param_b  = (const float*)d_in[2];
    const int*   w_rows   = (const int*)d_in[3];
    const int*   w_cols   = (const int*)d_in[4];
    const int*   w_params = (const int*)d_in[5];
    const int*   b_params = (const int*)d_in[6];
    float* out = (float*)d_out;

    int n = out_size;          // N = 262144
    int e = in_sizes[3];       // E = 16777216

    // 1) bias init
    {
        int threads = 256;
        int blocks = (n + threads - 1) / threads;
        bias_init_kernel<<<blocks, threads>>>(Param_b, b_params, out, n);
    }

    // 2) edge scatter, 4 edges per thread
    int e4 = e / 4;
    if (e4 > 0) {
        int threads = 256;
        int blocks = (e4 + threads - 1) / threads;
        edge_scatter_kernel<<<blocks, threads>>>(
            x, Param_W,
            (const int4*)w_rows, (const int4*)w_cols, (const int4*)w_params,
            out, e4);
    }

    int tail_start = e4 * 4;
    if (tail_start < e) {
        int rem = e - tail_start;
        int threads = 256;
        int blocks = (rem + threads - 1) / threads;
        edge_scatter_tail_kernel<<<blocks, threads>>>(
            x, Param_W, w_rows, w_cols, w_params, out, tail_start, e);
    }
}